// round 2
// baseline (speedup 1.0000x reference)
#include <cuda_runtime.h>
#include <math.h>

#define FH 50
#define FW 50
#define NPOS 2500
#define CIN 256
#define CMID 512
#define KDIM 2304          // 256*9
#define APER 9
#define NANCH 22500        // 2500*9
#define NSORT 32768
#define NHALF 16384
#define NPRE 6000
#define NPOST 300
#define NWORDS 94          // ceil(6000/64)
#define NMS_T 0.7f
#define MINSZ 16.0f

#define HPAD 56
#define WPAD 52
#define CHW  (HPAD*WPAD)   // 2912

// ---------------- scratch (device globals; zero-initialized) ----------------
__device__ float g_xpad[2 * CIN * CHW];                // padded input
__device__ float g_h[2 * CMID * NPOS];                 // conv1 output (relu)
__device__ __align__(16) float g_boxes[2 * NANCH * 4]; // decoded boxes
__device__ float g_scores[2 * NANCH];                  // filtered scores (or -1)
__device__ unsigned long long g_keys[2 * NSORT];       // sort keys
__device__ __align__(16) float g_boxes6k[2 * NPRE * 4];
__device__ float g_scores6k[2 * NPRE];
__device__ unsigned long long g_mask[(size_t)2 * NPRE * NWORDS];

// ---------------- pad input ----------------
__global__ __launch_bounds__(256) void pad_input_kernel(const float* __restrict__ x)
{
    const int idx = blockIdx.x * 256 + threadIdx.x;
    const int total = 2 * CIN * CHW;
    if (idx >= total) return;
    const int bc  = idx / CHW;          // b*256 + ci
    const int pos = idx - bc * CHW;
    const int iy  = pos / WPAD;
    const int ix  = pos - iy * WPAD;
    float v = 0.f;
    if (iy >= 1 && iy <= FH && ix >= 1 && ix <= FW)
        v = x[(size_t)bc * NPOS + (iy - 1) * FW + (ix - 1)];
    g_xpad[idx] = v;
}

// ---------------- conv 3x3 (implicit GEMM, fp32) ----------------
// M=512 (co), N=2500 (spatial), K=2304.  BM=128, BN=64, BK=16, 256 thr, 8x4/thread,
// double-buffered smem, one barrier per k-tile.
__global__ __launch_bounds__(256) void conv3x3_v2(
    const float* __restrict__ w, const float* __restrict__ bias)
{
    const int b   = blockIdx.z;
    const int co0 = blockIdx.y * 128;
    const int n0  = blockIdx.x * 64;
    const int t   = threadIdx.x;

    __shared__ __align__(16) float As[2][16][132];
    __shared__ __align__(16) float Bs[2][16][68];

    float acc[8][4];
#pragma unroll
    for (int i = 0; i < 8; i++)
#pragma unroll
        for (int j = 0; j < 4; j++) acc[i][j] = 0.f;

    const int ty = t >> 4;      // 0..15 : M rows ty*8
    const int tx = t & 15;      // 0..15 : N cols tx*4

    // A loader: thread -> row mA (0..127), k-chunk kcA in {0,8}
    const int mA  = t >> 1;
    const int kcA = (t & 1) * 8;
    // B loader: thread -> k row kB (0..15), 4 n columns
    const int kB  = t >> 4;
    const int nB0 = (t & 15) * 4;

    int bbase[4];
#pragma unroll
    for (int u = 0; u < 4; u++) {
        const int n = n0 + nB0 + u;
        int y, xx;
        if (n < NPOS) { y = n / FW; xx = n - y * FW; }
        else          { y = FH + 2; xx = 0; }            // rows 52..54 are all zero
        bbase[u] = (y /*+0*/) * WPAD + xx;               // iy = y+ky, ix = xx+kx
    }

    const float* xb   = g_xpad + (size_t)b * CIN * CHW;
    const float* wrow = w + (size_t)(co0 + mA) * KDIM + kcA;

    float4 a0, a1;
    float  bv[4];

    // prologue: load tile 0
    a0 = *(const float4*)(wrow + 0);
    a1 = *(const float4*)(wrow + 4);
    {
        const int k  = kB;
        const int ci = k / 9;
        const int r  = k - ci * 9;
        const int ky = r / 3, kx = r - ky * 3;
        const int off = ci * CHW + ky * WPAD + kx;
#pragma unroll
        for (int u = 0; u < 4; u++) bv[u] = xb[off + bbase[u]];
    }
    As[0][kcA + 0][mA] = a0.x; As[0][kcA + 1][mA] = a0.y;
    As[0][kcA + 2][mA] = a0.z; As[0][kcA + 3][mA] = a0.w;
    As[0][kcA + 4][mA] = a1.x; As[0][kcA + 5][mA] = a1.y;
    As[0][kcA + 6][mA] = a1.z; As[0][kcA + 7][mA] = a1.w;
#pragma unroll
    for (int u = 0; u < 4; u++) Bs[0][kB][nB0 + u] = bv[u];
    __syncthreads();

    const int NT = KDIM / 16;   // 144
    for (int kt = 0; kt < NT; ++kt) {
        const int p = kt & 1;
        const bool more = (kt + 1) < NT;
        if (more) {
            const int k0 = (kt + 1) * 16;
            a0 = *(const float4*)(wrow + k0);
            a1 = *(const float4*)(wrow + k0 + 4);
            const int k  = k0 + kB;
            const int ci = k / 9;
            const int r  = k - ci * 9;
            const int ky = r / 3, kx = r - ky * 3;
            const int off = ci * CHW + ky * WPAD + kx;
#pragma unroll
            for (int u = 0; u < 4; u++) bv[u] = xb[off + bbase[u]];
        }
#pragma unroll
        for (int kk = 0; kk < 16; kk++) {
            const float4 af0 = *(const float4*)&As[p][kk][ty * 8];
            const float4 af1 = *(const float4*)&As[p][kk][ty * 8 + 4];
            const float4 bf  = *(const float4*)&Bs[p][kk][tx * 4];
            const float ar[8] = {af0.x, af0.y, af0.z, af0.w, af1.x, af1.y, af1.z, af1.w};
            const float br[4] = {bf.x, bf.y, bf.z, bf.w};
#pragma unroll
            for (int i = 0; i < 8; i++)
#pragma unroll
                for (int j = 0; j < 4; j++) acc[i][j] += ar[i] * br[j];
        }
        if (more) {
            const int q = 1 - p;
            As[q][kcA + 0][mA] = a0.x; As[q][kcA + 1][mA] = a0.y;
            As[q][kcA + 2][mA] = a0.z; As[q][kcA + 3][mA] = a0.w;
            As[q][kcA + 4][mA] = a1.x; As[q][kcA + 5][mA] = a1.y;
            As[q][kcA + 6][mA] = a1.z; As[q][kcA + 7][mA] = a1.w;
#pragma unroll
            for (int u = 0; u < 4; u++) Bs[q][kB][nB0 + u] = bv[u];
            __syncthreads();
        }
    }

#pragma unroll
    for (int i = 0; i < 8; i++) {
        const int co = co0 + ty * 8 + i;
        const float bb = bias[co];
        float* hp = g_h + ((size_t)(b * CMID + co)) * NPOS;
#pragma unroll
        for (int j = 0; j < 4; j++) {
            const int n = n0 + tx * 4 + j;
            if (n < NPOS) {
                float v = acc[i][j] + bb;
                hp[n] = v > 0.f ? v : 0.f;
            }
        }
    }
}

// ---------------- heads: 1x1 convs + softmax + decode + key ----------------
__device__ __forceinline__ float to_dim(const int* p) {
    int v = *p;
    if (v > 0 && v < 100000) return (float)v;
    return __int_as_float(v);
}

__global__ __launch_bounds__(256) void heads_kernel(
    const float* __restrict__ ow, const float* __restrict__ ob,
    const float* __restrict__ lw, const float* __restrict__ lb,
    const float* __restrict__ anchors, const int* ihp, const int* iwp)
{
    const int b  = blockIdx.y;
    const int n0 = blockIdx.x * 16;
    const int t  = threadIdx.x;

    __shared__ float hs[CMID][17];
    __shared__ float outs[54][16];

    for (int idx = t; idx < CMID * 16; idx += 256) {
        const int c = idx >> 4, i = idx & 15;
        const int n = n0 + i;
        hs[c][i] = (n < NPOS) ? g_h[((size_t)(b * CMID + c)) * NPOS + n] : 0.f;
    }
    __syncthreads();

    {
        const int i = t & 15, g = t >> 4;
        float acc[4] = {0.f, 0.f, 0.f, 0.f};
        const float* wp[4];
        float bs[4];
#pragma unroll
        for (int s = 0; s < 4; s++) {
            const int oc = g + s * 16;
            if (oc < 18)       { wp[s] = ow + oc * CMID;        bs[s] = ob[oc]; }
            else if (oc < 54)  { wp[s] = lw + (oc - 18) * CMID; bs[s] = lb[oc - 18]; }
            else               { wp[s] = ow;                    bs[s] = 0.f; }
        }
#pragma unroll 4
        for (int c = 0; c < CMID; c++) {
            const float v = hs[c][i];
            acc[0] += wp[0][c] * v;
            acc[1] += wp[1][c] * v;
            acc[2] += wp[2][c] * v;
            acc[3] += wp[3][c] * v;
        }
#pragma unroll
        for (int s = 0; s < 4; s++) {
            const int oc = g + s * 16;
            if (oc < 54) outs[oc][i] = acc[s] + bs[s];
        }
    }
    __syncthreads();

    if (t < 144) {
        const int i = t & 15, a = t >> 4;
        const int n = n0 + i;
        if (n < NPOS) {
            const float imgw = to_dim(iwp), imgh = to_dim(ihp);
            const int m = n * APER + a;
            const float o0 = outs[2 * a][i], o1 = outs[2 * a + 1][i];
            const float mx = fmaxf(o0, o1);
            const float e0 = expf(o0 - mx), e1 = expf(o1 - mx);
            const float sc = e1 / (e0 + e1);

            const float l0 = outs[18 + 4 * a + 0][i];
            const float l1 = outs[18 + 4 * a + 1][i];
            const float l2 = outs[18 + 4 * a + 2][i];
            const float l3 = outs[18 + 4 * a + 3][i];

            const float a0 = anchors[m * 4 + 0], a1 = anchors[m * 4 + 1];
            const float a2 = anchors[m * 4 + 2], a3 = anchors[m * 4 + 3];
            const float aw = a2 - a0, ah = a3 - a1;
            const float acx = a0 + 0.5f * aw, acy = a1 + 0.5f * ah;
            const float cx = acx + l0 * aw, cy = acy + l1 * ah;
            const float wd = aw * expf(l2), hh = ah * expf(l3);
            float x1 = fminf(fmaxf(cx - 0.5f * wd, 0.f), imgw);
            float y1 = fminf(fmaxf(cy - 0.5f * hh, 0.f), imgh);
            float x2 = fminf(fmaxf(cx + 0.5f * wd, 0.f), imgw);
            float y2 = fminf(fmaxf(cy + 0.5f * hh, 0.f), imgh);

            const bool valid = (x2 - x1 >= MINSZ) && (y2 - y1 >= MINSZ);
            const float s2 = valid ? sc : -1.f;

            float* bp = g_boxes + ((size_t)(b * NANCH + m)) * 4;
            bp[0] = x1; bp[1] = y1; bp[2] = x2; bp[3] = y2;
            g_scores[b * NANCH + m] = s2;

            const unsigned sb = __float_as_uint(s2);
            const unsigned mono = (sb & 0x80000000u) ? ~sb : (sb | 0x80000000u);
            g_keys[b * NSORT + m] =
                ((unsigned long long)mono << 32) |
                (unsigned long long)(0xFFFFFFFFu - (unsigned)m);
        }
    }
}

// ---------------- single-kernel sort + gather (one block per batch) ----------------
// Bitonic over 32768 keys, descending; only the top half is fully merged (bitonic
// split property: after the j=16384 cross step, the max half contains the top 16384).
// Top 6000 gathered straight from smem.
__device__ __forceinline__ void sort_levels_smem(
    unsigned long long* sk, int t, int gbias, int kmax)
{
    for (int k = 2; k <= kmax; k <<= 1) {
        for (int j = k >> 1; j > 0; j >>= 1) {
#pragma unroll 1
            for (int s = 0; s < NHALF / 2 / 1024; s++) {
                const int c = t + s * 1024;
                const int i = ((c & ~(j - 1)) << 1) | (c & (j - 1));
                const int p = i + j;
                const bool desc = (((gbias + i) & k) == 0);
                unsigned long long a = sk[i], bb = sk[p];
                const bool sw = desc ? (a < bb) : (a > bb);
                if (sw) { sk[i] = bb; sk[p] = a; }
            }
            __syncthreads();
        }
    }
}

__global__ __launch_bounds__(1024) void sort_gather_kernel()
{
    extern __shared__ unsigned long long sk[];   // 16384 keys = 128 KB
    const int b = blockIdx.x;
    const int t = threadIdx.x;
    unsigned long long* gk = g_keys + b * NSORT;

    // ---- half 1: load (with pad), sort (ascending run), store ----
    for (int i = t; i < NHALF; i += 1024) {
        const int gi = NHALF + i;
        sk[i] = (gi < NANCH) ? gk[gi] : 0ull;
    }
    __syncthreads();
    sort_levels_smem(sk, t, NHALF, NHALF);
    for (int i = t; i < NHALF; i += 1024) gk[NHALF + i] = sk[i];
    __syncthreads();

    // ---- half 0: load, sort (descending run) ----
    for (int i = t; i < NHALF; i += 1024) sk[i] = gk[i];
    __syncthreads();
    sort_levels_smem(sk, t, 0, NHALF);

    // ---- cross step (j=16384): keep the max element of each pair ----
    for (int i = t; i < NHALF; i += 1024) {
        const unsigned long long o = gk[NHALF + i];
        if (sk[i] < o) sk[i] = o;
    }
    __syncthreads();

    // ---- final merge within the max half: j = 8192..1, all descending ----
    for (int j = NHALF / 2; j > 0; j >>= 1) {
#pragma unroll 1
        for (int s = 0; s < NHALF / 2 / 1024; s++) {
            const int c = t + s * 1024;
            const int i = ((c & ~(j - 1)) << 1) | (c & (j - 1));
            const int p = i + j;
            unsigned long long a = sk[i], bb = sk[p];
            if (a < bb) { sk[i] = bb; sk[p] = a; }
        }
        __syncthreads();
    }

    // ---- gather top 6000 ----
    for (int r = t; r < NPRE; r += 1024) {
        const unsigned long long key = sk[r];
        const unsigned idx = 0xFFFFFFFFu - (unsigned)(key & 0xFFFFFFFFull);
        const float4 v = *(const float4*)&g_boxes[((size_t)(b * NANCH + idx)) * 4];
        *(float4*)&g_boxes6k[((size_t)(b * NPRE + r)) * 4] = v;
        g_scores6k[b * NPRE + r] = g_scores[b * NANCH + idx];
    }
}

// ---------------- NMS suppression masks ----------------
__global__ __launch_bounds__(64) void nms_mask_kernel() {
    const int cb = blockIdx.x, rb = blockIdx.y, b = blockIdx.z;
    if (cb < rb) return;
    __shared__ float4 cbox[64];
    __shared__ float carea[64];
    const int t = threadIdx.x;
    const int j0 = cb * 64 + t;
    if (j0 < NPRE) {
        float4 v = *(const float4*)&g_boxes6k[((size_t)(b * NPRE + j0)) * 4];
        cbox[t] = v;
        carea[t] = (v.z - v.x) * (v.w - v.y);
    }
    __syncthreads();
    const int i = rb * 64 + t;
    if (i >= NPRE) return;
    const float4 bi = *(const float4*)&g_boxes6k[((size_t)(b * NPRE + i)) * 4];
    const float ai = (bi.z - bi.x) * (bi.w - bi.y);
    unsigned long long bits = 0ull;
    const int jmax = min(64, NPRE - cb * 64);
    for (int jj = 0; jj < jmax; jj++) {
        const int jg = cb * 64 + jj;
        if (jg <= i) continue;
        const float4 bj = cbox[jj];
        const float ix1 = fmaxf(bi.x, bj.x), iy1 = fmaxf(bi.y, bj.y);
        const float ix2 = fminf(bi.z, bj.z), iy2 = fminf(bi.w, bj.w);
        const float inter = fmaxf(ix2 - ix1, 0.f) * fmaxf(iy2 - iy1, 0.f);
        const float iou = inter / (ai + carea[jj] - inter);
        if (iou > NMS_T) bits |= 1ull << jj;
    }
    g_mask[((size_t)(b * NPRE + i)) * NWORDS + cb] = bits;
}

// ---------------- sequential selection + output ----------------
__global__ __launch_bounds__(128) void select_out_kernel(float* __restrict__ out) {
    const int b = blockIdx.x;
    const int t = threadIdx.x;
    __shared__ unsigned long long removed[NWORDS];
    __shared__ int keep[NPOST];
    __shared__ int s_count;
    if (t < NWORDS) removed[t] = 0ull;
    if (t == 0) s_count = 0;
    __syncthreads();

    if (t < 32) {
        const int lane = t;
        int count = 0;
        bool done = false;
        for (int c = 0; c < NWORDS && !done; c++) {
            unsigned long long live = 0ull;
            if (lane == 0) {
                live = ~removed[c];
                if (c == NWORDS - 1) live &= ((1ull << (NPRE - 64 * (NWORDS - 1))) - 1ull);
            }
            while (true) {
                int bitpos = -1;
                if (lane == 0) bitpos = live ? (__ffsll((long long)live) - 1) : -1;
                bitpos = __shfl_sync(0xffffffffu, bitpos, 0);
                if (bitpos < 0) break;
                const int idx = c * 64 + bitpos;
                const float sc = g_scores6k[b * NPRE + idx];
                if (sc < 0.f) { done = true; break; }
                if (lane == 0) keep[count] = idx;
                count++;
                if (count >= NPOST) { done = true; break; }
                const unsigned long long* mrow =
                    g_mask + ((size_t)(b * NPRE + idx)) * NWORDS;
                for (int wdx = lane; wdx < NWORDS; wdx += 32) removed[wdx] |= mrow[wdx];
                __syncwarp();
                if (lane == 0) {
                    live &= ~(1ull << bitpos);
                    live &= ~mrow[c];
                }
            }
        }
        if (lane == 0) s_count = count;
    }
    __syncthreads();

    const int cnt = s_count;
    for (int r = t; r < NPOST; r += 128) {
        float bx0 = 0.f, bx1 = 0.f, bx2 = 0.f, bx3 = 0.f, sv = 0.f, mv = 0.f;
        if (r < cnt) {
            const int i = keep[r];
            const float* bp = g_boxes6k + ((size_t)(b * NPRE + i)) * 4;
            bx0 = bp[0]; bx1 = bp[1]; bx2 = bp[2]; bx3 = bp[3];
            sv = g_scores6k[b * NPRE + i];
            mv = 1.f;
        }
        float* ob = out + b * (NPOST * 4) + r * 4;
        ob[0] = bx0; ob[1] = bx1; ob[2] = bx2; ob[3] = bx3;
        out[2 * NPOST * 4 + b * NPOST + r] = sv;
        out[2 * NPOST * 4 + 2 * NPOST + b * NPOST + r] = mv;
    }
}

// ---------------- launch ----------------
extern "C" void kernel_launch(void* const* d_in, const int* in_sizes, int n_in,
                              void* d_out, int out_size)
{
    const float* x   = (const float*)d_in[0];
    const float* c1w = (const float*)d_in[1];
    const float* c1b = (const float*)d_in[2];
    const float* ow  = (const float*)d_in[3];
    const float* ob  = (const float*)d_in[4];
    const float* lw  = (const float*)d_in[5];
    const float* lb  = (const float*)d_in[6];
    const float* anc = (const float*)d_in[7];
    const int*   ih  = (const int*)d_in[8];
    const int*   iw  = (const int*)d_in[9];
    float* out = (float*)d_out;

    static bool attr_set = false;
    if (!attr_set) {
        cudaFuncSetAttribute(sort_gather_kernel,
                             cudaFuncAttributeMaxDynamicSharedMemorySize,
                             NHALF * (int)sizeof(unsigned long long));
        attr_set = true;
    }

    const int pad_total = 2 * CIN * CHW;
    pad_input_kernel<<<(pad_total + 255) / 256, 256>>>(x);
    conv3x3_v2<<<dim3(40, 4, 2), 256>>>(c1w, c1b);
    heads_kernel<<<dim3(157, 2), 256>>>(ow, ob, lw, lb, anc, ih, iw);
    sort_gather_kernel<<<2, 1024, NHALF * sizeof(unsigned long long)>>>();
    nms_mask_kernel<<<dim3(NWORDS, NWORDS, 2), 64>>>();
    select_out_kernel<<<2, 128>>>(out);
}

// round 3
// speedup vs baseline: 1.3120x; 1.3120x over previous
#include <cuda_runtime.h>
#include <math.h>

#define FH 50
#define FW 50
#define NPOS 2500
#define CIN 256
#define CMID 512
#define KDIM 2304          // 256*9
#define KHALF 1152
#define APER 9
#define NANCH 22500        // 2500*9
#define NPRE 6000
#define NPOST 300
#define NSORT2 8192
#define NWORDS 94          // ceil(6000/64)
#define NMS_T 0.7f
#define MINSZ 16.0f

#define HPAD 56
#define WPAD 52
#define CHW  (HPAD*WPAD)   // 2912

// ---------------- scratch (device globals; zero-initialized at load) ----------------
__device__ float g_xpad[2 * CIN * CHW];                   // padded input
__device__ float g_hpart[2 * 2 * CMID * NPOS];            // conv partial sums [khalf][b][c][n]
__device__ __align__(16) float g_boxes[2 * NANCH * 4];
__device__ float g_scores[2 * NANCH];
__device__ unsigned long long g_keys[2 * NANCH];
__device__ int g_hist[3][2][65536];
__device__ int g_T[3][2];
__device__ int g_G[3][2];
__device__ int g_cnt[2];
__device__ unsigned long long g_cand[2][NPRE];
__device__ __align__(16) float g_boxes6k[2 * NPRE * 4];
__device__ float g_scores6k[2 * NPRE];
__device__ unsigned long long g_mask[(size_t)2 * NPRE * NWORDS];

// ---------------- zero histograms + counters (every replay) ----------------
__global__ __launch_bounds__(1024) void zero_kernel()
{
    const int idx = blockIdx.x * 1024 + threadIdx.x;
    const int nh = 3 * 2 * 65536;
    if (idx < nh) ((int*)g_hist)[idx] = 0;
    if (idx < 2) g_cnt[idx] = 0;
}

// ---------------- pad input ----------------
__global__ __launch_bounds__(256) void pad_input_kernel(const float* __restrict__ x)
{
    const int idx = blockIdx.x * 256 + threadIdx.x;
    const int total = 2 * CIN * CHW;
    if (idx >= total) return;
    const int bc  = idx / CHW;
    const int pos = idx - bc * CHW;
    const int iy  = pos / WPAD;
    const int ix  = pos - iy * WPAD;
    float v = 0.f;
    if (iy >= 1 && iy <= FH && ix >= 1 && ix <= FW)
        v = x[(size_t)bc * NPOS + (iy - 1) * FW + (ix - 1)];
    g_xpad[idx] = v;
}

// ---------------- conv 3x3, K-split x2 (implicit GEMM, fp32) ----------------
// BM=128, BN=64, BK=16, 256 thr, 8x4/thread, double-buffered, K=1152 per block.
__global__ __launch_bounds__(256) void conv3x3_v3(const float* __restrict__ w)
{
    const int b    = blockIdx.z;
    const int mt   = blockIdx.y & 3;
    const int kh   = blockIdx.y >> 2;
    const int co0  = mt * 128;
    const int n0   = blockIdx.x * 64;
    const int t    = threadIdx.x;
    const int kbase = kh * KHALF;

    __shared__ __align__(16) float As[2][16][132];
    __shared__ __align__(16) float Bs[2][16][68];

    float acc[8][4];
#pragma unroll
    for (int i = 0; i < 8; i++)
#pragma unroll
        for (int j = 0; j < 4; j++) acc[i][j] = 0.f;

    const int ty = t >> 4;
    const int tx = t & 15;
    const int mA  = t >> 1;
    const int kcA = (t & 1) * 8;
    const int kB  = t >> 4;
    const int nB0 = (t & 15) * 4;

    int bbase[4];
#pragma unroll
    for (int u = 0; u < 4; u++) {
        const int n = n0 + nB0 + u;
        int y, xx;
        if (n < NPOS) { y = n / FW; xx = n - y * FW; }
        else          { y = FH + 2; xx = 0; }
        bbase[u] = y * WPAD + xx;
    }

    const float* xb   = g_xpad + (size_t)b * CIN * CHW;
    const float* wrow = w + (size_t)(co0 + mA) * KDIM + kbase + kcA;

    float4 a0, a1;
    float  bv[4];

    a0 = *(const float4*)(wrow + 0);
    a1 = *(const float4*)(wrow + 4);
    {
        const int k  = kbase + kB;
        const int ci = k / 9;
        const int r  = k - ci * 9;
        const int ky = r / 3, kx = r - ky * 3;
        const int off = ci * CHW + ky * WPAD + kx;
#pragma unroll
        for (int u = 0; u < 4; u++) bv[u] = xb[off + bbase[u]];
    }
    As[0][kcA + 0][mA] = a0.x; As[0][kcA + 1][mA] = a0.y;
    As[0][kcA + 2][mA] = a0.z; As[0][kcA + 3][mA] = a0.w;
    As[0][kcA + 4][mA] = a1.x; As[0][kcA + 5][mA] = a1.y;
    As[0][kcA + 6][mA] = a1.z; As[0][kcA + 7][mA] = a1.w;
#pragma unroll
    for (int u = 0; u < 4; u++) Bs[0][kB][nB0 + u] = bv[u];
    __syncthreads();

    const int NT = KHALF / 16;   // 72
    for (int kt = 0; kt < NT; ++kt) {
        const int p = kt & 1;
        const bool more = (kt + 1) < NT;
        if (more) {
            const int k0 = (kt + 1) * 16;
            a0 = *(const float4*)(wrow + k0);
            a1 = *(const float4*)(wrow + k0 + 4);
            const int k  = kbase + k0 + kB;
            const int ci = k / 9;
            const int r  = k - ci * 9;
            const int ky = r / 3, kx = r - ky * 3;
            const int off = ci * CHW + ky * WPAD + kx;
#pragma unroll
            for (int u = 0; u < 4; u++) bv[u] = xb[off + bbase[u]];
        }
#pragma unroll
        for (int kk = 0; kk < 16; kk++) {
            const float4 af0 = *(const float4*)&As[p][kk][ty * 8];
            const float4 af1 = *(const float4*)&As[p][kk][ty * 8 + 4];
            const float4 bf  = *(const float4*)&Bs[p][kk][tx * 4];
            const float ar[8] = {af0.x, af0.y, af0.z, af0.w, af1.x, af1.y, af1.z, af1.w};
            const float br[4] = {bf.x, bf.y, bf.z, bf.w};
#pragma unroll
            for (int i = 0; i < 8; i++)
#pragma unroll
                for (int j = 0; j < 4; j++) acc[i][j] += ar[i] * br[j];
        }
        if (more) {
            const int q = 1 - p;
            As[q][kcA + 0][mA] = a0.x; As[q][kcA + 1][mA] = a0.y;
            As[q][kcA + 2][mA] = a0.z; As[q][kcA + 3][mA] = a0.w;
            As[q][kcA + 4][mA] = a1.x; As[q][kcA + 5][mA] = a1.y;
            As[q][kcA + 6][mA] = a1.z; As[q][kcA + 7][mA] = a1.w;
#pragma unroll
            for (int u = 0; u < 4; u++) Bs[q][kB][nB0 + u] = bv[u];
            __syncthreads();
        }
    }

#pragma unroll
    for (int i = 0; i < 8; i++) {
        const int co = co0 + ty * 8 + i;
        float* hp = g_hpart + ((size_t)((kh * 2 + b) * CMID + co)) * NPOS;
#pragma unroll
        for (int j = 0; j < 4; j++) {
            const int n = n0 + tx * 4 + j;
            if (n < NPOS) hp[n] = acc[i][j];
        }
    }
}

// ---------------- heads: sum partials + bias + relu, 1x1 convs, decode, keys ----------------
__device__ __forceinline__ float to_dim(const int* p) {
    int v = *p;
    if (v > 0 && v < 100000) return (float)v;
    return __int_as_float(v);
}

__global__ __launch_bounds__(256) void heads_kernel(
    const float* __restrict__ c1b,
    const float* __restrict__ ow, const float* __restrict__ ob,
    const float* __restrict__ lw, const float* __restrict__ lb,
    const float* __restrict__ anchors, const int* ihp, const int* iwp)
{
    const int b  = blockIdx.y;
    const int n0 = blockIdx.x * 16;
    const int t  = threadIdx.x;

    __shared__ float hs[CMID][17];
    __shared__ float outs[54][16];

    for (int idx = t; idx < CMID * 16; idx += 256) {
        const int c = idx >> 4, i = idx & 15;
        const int n = n0 + i;
        float v = 0.f;
        if (n < NPOS) {
            const float h0 = g_hpart[((size_t)((0 * 2 + b) * CMID + c)) * NPOS + n];
            const float h1 = g_hpart[((size_t)((1 * 2 + b) * CMID + c)) * NPOS + n];
            v = h0 + h1 + c1b[c];
            v = v > 0.f ? v : 0.f;
        }
        hs[c][i] = v;
    }
    __syncthreads();

    {
        const int i = t & 15, g = t >> 4;
        float acc[4] = {0.f, 0.f, 0.f, 0.f};
        const float* wp[4];
        float bs[4];
#pragma unroll
        for (int s = 0; s < 4; s++) {
            const int oc = g + s * 16;
            if (oc < 18)       { wp[s] = ow + oc * CMID;        bs[s] = ob[oc]; }
            else if (oc < 54)  { wp[s] = lw + (oc - 18) * CMID; bs[s] = lb[oc - 18]; }
            else               { wp[s] = ow;                    bs[s] = 0.f; }
        }
#pragma unroll 4
        for (int c = 0; c < CMID; c++) {
            const float v = hs[c][i];
            acc[0] += wp[0][c] * v;
            acc[1] += wp[1][c] * v;
            acc[2] += wp[2][c] * v;
            acc[3] += wp[3][c] * v;
        }
#pragma unroll
        for (int s = 0; s < 4; s++) {
            const int oc = g + s * 16;
            if (oc < 54) outs[oc][i] = acc[s] + bs[s];
        }
    }
    __syncthreads();

    if (t < 144) {
        const int i = t & 15, a = t >> 4;
        const int n = n0 + i;
        if (n < NPOS) {
            const float imgw = to_dim(iwp), imgh = to_dim(ihp);
            const int m = n * APER + a;
            const float o0 = outs[2 * a][i], o1 = outs[2 * a + 1][i];
            const float mx = fmaxf(o0, o1);
            const float e0 = expf(o0 - mx), e1 = expf(o1 - mx);
            const float sc = e1 / (e0 + e1);

            const float l0 = outs[18 + 4 * a + 0][i];
            const float l1 = outs[18 + 4 * a + 1][i];
            const float l2 = outs[18 + 4 * a + 2][i];
            const float l3 = outs[18 + 4 * a + 3][i];

            const float a0 = anchors[m * 4 + 0], a1 = anchors[m * 4 + 1];
            const float a2 = anchors[m * 4 + 2], a3 = anchors[m * 4 + 3];
            const float aw = a2 - a0, ah = a3 - a1;
            const float acx = a0 + 0.5f * aw, acy = a1 + 0.5f * ah;
            const float cx = acx + l0 * aw, cy = acy + l1 * ah;
            const float wd = aw * expf(l2), hh = ah * expf(l3);
            float x1 = fminf(fmaxf(cx - 0.5f * wd, 0.f), imgw);
            float y1 = fminf(fmaxf(cy - 0.5f * hh, 0.f), imgh);
            float x2 = fminf(fmaxf(cx + 0.5f * wd, 0.f), imgw);
            float y2 = fminf(fmaxf(cy + 0.5f * hh, 0.f), imgh);

            const bool valid = (x2 - x1 >= MINSZ) && (y2 - y1 >= MINSZ);
            const float s2 = valid ? sc : -1.f;

            float* bp = g_boxes + ((size_t)(b * NANCH + m)) * 4;
            bp[0] = x1; bp[1] = y1; bp[2] = x2; bp[3] = y2;
            g_scores[b * NANCH + m] = s2;

            const unsigned sb = __float_as_uint(s2);
            const unsigned mono = (sb & 0x80000000u) ? ~sb : (sb | 0x80000000u);
            g_keys[b * NANCH + m] =
                ((unsigned long long)mono << 32) |
                (unsigned long long)(0xFFFFFFFFu - (unsigned)m);
        }
    }
}

// ---------------- radix select: 3-level histogram → exactly top-6000 ----------------
__global__ __launch_bounds__(256) void hist_kernel(int level)
{
    const int tid = blockIdx.x * 256 + threadIdx.x;
    const bool active = tid < 2 * NANCH;
    int b = 0; unsigned long long key = 0;
    if (active) {
        b = tid / NANCH;
        key = g_keys[b * NANCH + (tid - b * NANCH)];
    }
    const int b1 = (int)(key >> 48);
    const int b2 = (int)((key >> 32) & 0xFFFF);
    const int b3 = (int)(key & 0xFFFF);

    if (level == 0) {
        const unsigned act = __ballot_sync(0xffffffffu, active);
        if (active) {
            const int tag = (b << 16) | b1;
            const unsigned mm = __match_any_sync(act, tag);
            const int leader = __ffs(mm) - 1;
            if ((threadIdx.x & 31) == leader)
                atomicAdd(&g_hist[0][b][b1], __popc(mm));
        }
    } else if (level == 1) {
        if (active && b1 == g_T[0][b]) atomicAdd(&g_hist[1][b][b2], 1);
    } else {
        if (active && b1 == g_T[0][b] && b2 == g_T[1][b]) atomicAdd(&g_hist[2][b][b3], 1);
    }
}

__global__ __launch_bounds__(1024) void scan_kernel(int level)
{
    const int b = blockIdx.x;
    const int s = threadIdx.x;
    const int* hist = g_hist[level][b];

    __shared__ int a[1024];
    __shared__ int strip[1024];

    int sum = 0;
    const int4* h4 = (const int4*)(hist + s * 64);
#pragma unroll
    for (int q = 0; q < 16; q++) { int4 v = h4[q]; sum += v.x + v.y + v.z + v.w; }
    strip[s] = sum; a[s] = sum;
    __syncthreads();
    for (int off = 1; off < 1024; off <<= 1) {
        const int v = (s + off < 1024) ? a[s + off] : 0;
        __syncthreads();
        a[s] += v;
        __syncthreads();
    }

    int budget = NPRE;
    if (level >= 1) budget -= g_G[0][b];
    if (level >= 2) budget -= g_G[1][b];

    const int nxt = (s < 1023) ? a[s + 1] : 0;
    if (a[s] >= budget && nxt < budget) {
        int vals[64];
#pragma unroll
        for (int q = 0; q < 16; q++) {
            int4 v = h4[q];
            vals[q * 4] = v.x; vals[q * 4 + 1] = v.y; vals[q * 4 + 2] = v.z; vals[q * 4 + 3] = v.w;
        }
        int run = nxt, T = -1, G = 0;
#pragma unroll
        for (int v = 63; v >= 0; v--) {
            run += vals[v];
            if (run >= budget) { T = s * 64 + v; G = run - vals[v]; break; }
        }
        g_T[level][b] = T; g_G[level][b] = G;
    }
}

__global__ __launch_bounds__(256) void compact_kernel()
{
    const int tid = blockIdx.x * 256 + threadIdx.x;
    if (tid >= 2 * NANCH) return;
    const int b = tid / NANCH;
    const unsigned long long key = g_keys[b * NANCH + (tid - b * NANCH)];
    const int b1 = (int)(key >> 48);
    const int b2 = (int)((key >> 32) & 0xFFFF);
    const int b3 = (int)(key & 0xFFFF);
    const int T1 = g_T[0][b], T2 = g_T[1][b], T3 = g_T[2][b];
    const bool keep = (b1 > T1) ||
                      (b1 == T1 && (b2 > T2 || (b2 == T2 && b3 >= T3)));
    if (keep) {
        const int slot = atomicAdd(&g_cnt[b], 1);
        g_cand[b][slot] = key;
    }
}

// ---------------- sort 6000 candidates (pad 8192) + gather ----------------
__global__ __launch_bounds__(1024) void sort_gather2()
{
    extern __shared__ unsigned long long sk[];   // 8192 keys = 64 KB
    const int b = blockIdx.x;
    const int t = threadIdx.x;

    for (int i = t; i < NSORT2; i += 1024)
        sk[i] = (i < NPRE) ? g_cand[b][i] : 0ull;
    __syncthreads();

    for (int k = 2; k <= NSORT2; k <<= 1) {
        for (int j = k >> 1; j > 0; j >>= 1) {
#pragma unroll
            for (int s = 0; s < 4; s++) {
                const int c = t + s * 1024;
                const int i = ((c & ~(j - 1)) << 1) | (c & (j - 1));
                const int p = i + j;
                const bool desc = ((i & k) == 0);
                const unsigned long long x = sk[i], y = sk[p];
                const bool sw = desc ? (x < y) : (x > y);
                if (sw) { sk[i] = y; sk[p] = x; }
            }
            __syncthreads();
        }
    }

    for (int r = t; r < NPRE; r += 1024) {
        const unsigned long long key = sk[r];
        const unsigned idx = 0xFFFFFFFFu - (unsigned)(key & 0xFFFFFFFFull);
        const float4 v = *(const float4*)&g_boxes[((size_t)(b * NANCH + idx)) * 4];
        *(float4*)&g_boxes6k[((size_t)(b * NPRE + r)) * 4] = v;
        g_scores6k[b * NPRE + r] = g_scores[b * NANCH + idx];
    }
}

// ---------------- NMS suppression masks ----------------
__global__ __launch_bounds__(64) void nms_mask_kernel() {
    const int cb = blockIdx.x, rb = blockIdx.y, b = blockIdx.z;
    if (cb < rb) return;
    __shared__ float4 cbox[64];
    __shared__ float carea[64];
    const int t = threadIdx.x;
    const int j0 = cb * 64 + t;
    if (j0 < NPRE) {
        float4 v = *(const float4*)&g_boxes6k[((size_t)(b * NPRE + j0)) * 4];
        cbox[t] = v;
        carea[t] = (v.z - v.x) * (v.w - v.y);
    }
    __syncthreads();
    const int i = rb * 64 + t;
    if (i >= NPRE) return;
    const float4 bi = *(const float4*)&g_boxes6k[((size_t)(b * NPRE + i)) * 4];
    const float ai = (bi.z - bi.x) * (bi.w - bi.y);
    unsigned long long bits = 0ull;
    const int jmax = min(64, NPRE - cb * 64);
    for (int jj = 0; jj < jmax; jj++) {
        const int jg = cb * 64 + jj;
        if (jg <= i) continue;
        const float4 bj = cbox[jj];
        const float ix1 = fmaxf(bi.x, bj.x), iy1 = fmaxf(bi.y, bj.y);
        const float ix2 = fminf(bi.z, bj.z), iy2 = fminf(bi.w, bj.w);
        const float inter = fmaxf(ix2 - ix1, 0.f) * fmaxf(iy2 - iy1, 0.f);
        const float iou = inter / (ai + carea[jj] - inter);
        if (iou > NMS_T) bits |= 1ull << jj;
    }
    g_mask[((size_t)(b * NPRE + i)) * NWORDS + cb] = bits;
}

// ---------------- sequential selection + output ----------------
__global__ __launch_bounds__(128) void select_out_kernel(float* __restrict__ out) {
    const int b = blockIdx.x;
    const int t = threadIdx.x;
    __shared__ unsigned long long removed[NWORDS];
    __shared__ int keep[NPOST];
    __shared__ int s_count;
    if (t < NWORDS) removed[t] = 0ull;
    if (t == 0) s_count = 0;
    __syncthreads();

    if (t < 32) {
        const int lane = t;
        int count = 0;
        bool done = false;
        for (int c = 0; c < NWORDS && !done; c++) {
            unsigned long long live = 0ull;
            if (lane == 0) {
                live = ~removed[c];
                if (c == NWORDS - 1) live &= ((1ull << (NPRE - 64 * (NWORDS - 1))) - 1ull);
            }
            while (true) {
                int bitpos = -1;
                if (lane == 0) bitpos = live ? (__ffsll((long long)live) - 1) : -1;
                bitpos = __shfl_sync(0xffffffffu, bitpos, 0);
                if (bitpos < 0) break;
                const int idx = c * 64 + bitpos;
                const float sc = g_scores6k[b * NPRE + idx];
                if (sc < 0.f) { done = true; break; }
                if (lane == 0) keep[count] = idx;
                count++;
                if (count >= NPOST) { done = true; break; }
                const unsigned long long* mrow =
                    g_mask + ((size_t)(b * NPRE + idx)) * NWORDS;
                for (int wdx = lane; wdx < NWORDS; wdx += 32) removed[wdx] |= mrow[wdx];
                __syncwarp();
                if (lane == 0) {
                    live &= ~(1ull << bitpos);
                    live &= ~mrow[c];
                }
            }
        }
        if (lane == 0) s_count = count;
    }
    __syncthreads();

    const int cnt = s_count;
    for (int r = t; r < NPOST; r += 128) {
        float bx0 = 0.f, bx1 = 0.f, bx2 = 0.f, bx3 = 0.f, sv = 0.f, mv = 0.f;
        if (r < cnt) {
            const int i = keep[r];
            const float* bp = g_boxes6k + ((size_t)(b * NPRE + i)) * 4;
            bx0 = bp[0]; bx1 = bp[1]; bx2 = bp[2]; bx3 = bp[3];
            sv = g_scores6k[b * NPRE + i];
            mv = 1.f;
        }
        float* ob = out + b * (NPOST * 4) + r * 4;
        ob[0] = bx0; ob[1] = bx1; ob[2] = bx2; ob[3] = bx3;
        out[2 * NPOST * 4 + b * NPOST + r] = sv;
        out[2 * NPOST * 4 + 2 * NPOST + b * NPOST + r] = mv;
    }
}

// ---------------- launch ----------------
extern "C" void kernel_launch(void* const* d_in, const int* in_sizes, int n_in,
                              void* d_out, int out_size)
{
    const float* x   = (const float*)d_in[0];
    const float* c1w = (const float*)d_in[1];
    const float* c1b = (const float*)d_in[2];
    const float* ow  = (const float*)d_in[3];
    const float* ob  = (const float*)d_in[4];
    const float* lw  = (const float*)d_in[5];
    const float* lb  = (const float*)d_in[6];
    const float* anc = (const float*)d_in[7];
    const int*   ih  = (const int*)d_in[8];
    const int*   iw  = (const int*)d_in[9];
    float* out = (float*)d_out;

    static bool attr_set = false;
    if (!attr_set) {
        cudaFuncSetAttribute(sort_gather2,
                             cudaFuncAttributeMaxDynamicSharedMemorySize,
                             NSORT2 * (int)sizeof(unsigned long long));
        attr_set = true;
    }

    zero_kernel<<<(3 * 2 * 65536 + 1023) / 1024, 1024>>>();
    const int pad_total = 2 * CIN * CHW;
    pad_input_kernel<<<(pad_total + 255) / 256, 256>>>(x);
    conv3x3_v3<<<dim3(40, 8, 2), 256>>>(c1w);
    heads_kernel<<<dim3(157, 2), 256>>>(c1b, ow, ob, lw, lb, anc, ih, iw);

    const int ng = (2 * NANCH + 255) / 256;
    hist_kernel<<<ng, 256>>>(0);
    scan_kernel<<<2, 1024>>>(0);
    hist_kernel<<<ng, 256>>>(1);
    scan_kernel<<<2, 1024>>>(1);
    hist_kernel<<<ng, 256>>>(2);
    scan_kernel<<<2, 1024>>>(2);
    compact_kernel<<<ng, 256>>>();

    sort_gather2<<<2, 1024, NSORT2 * sizeof(unsigned long long)>>>();
    nms_mask_kernel<<<dim3(NWORDS, NWORDS, 2), 64>>>();
    select_out_kernel<<<2, 128>>>(out);
}